// round 7
// baseline (speedup 1.0000x reference)
#include <cuda_runtime.h>
#include <cuda_bf16.h>
#include <cstdint>

// INT4 symmetric grouped dequant — 256-bit ld/st, roofline-margin tuning.
//   packed: TOTAL/2 int32 (one byte each, two nibbles: low = even elem, high = odd)
//   scale:  (4096, 86) fp32, group size 128
//   out:    fp32, out[i] = (nibble - 8) * scale[i/128]
//
// One 32B v8 load (16 codes) + two 32B v8 stores per thread.
// group = t >> 3 (16 codes * 8 threads = 128 = one scale group).
// Loads: evict-first (.cs) — read-once stream, don't pollute L2.
// Stores: DEFAULT policy — let L2 writeback lazily instead of eager
// evict-first bursts that fight the read stream for DRAM turnaround.
// 512-thread blocks: 32KB contiguous write region per block for better
// HBM row-buffer locality.

#define N_PACKED   22544384              // TOTAL/2 int32s
#define N_V8       (N_PACKED / 8)        // 2,818,048 threads
#define THREADS    512
#define BLOCKS     (N_V8 / THREADS)      // 5504 exact

__global__ void __launch_bounds__(THREADS)
int4_dequant_kernel(const uint32_t* __restrict__ packed,
                    const float* __restrict__ scale,
                    float* __restrict__ out)
{
    const int t = blockIdx.x * THREADS + threadIdx.x;

    const float s = __ldg(&scale[t >> 3]);   // cached, 128x reuse

    uint32_t p[8];
    asm volatile(
        "ld.global.cs.v8.b32 {%0,%1,%2,%3,%4,%5,%6,%7}, [%8];"
        : "=r"(p[0]), "=r"(p[1]), "=r"(p[2]), "=r"(p[3]),
          "=r"(p[4]), "=r"(p[5]), "=r"(p[6]), "=r"(p[7])
        : "l"(packed + 8 * (size_t)t));

    float f[16];
#pragma unroll
    for (int j = 0; j < 8; ++j) {
        f[2 * j]     = (float)((int)( p[j]       & 15u) - 8) * s;
        f[2 * j + 1] = (float)((int)((p[j] >> 4) & 15u) - 8) * s;
    }

    float* o = out + 16 * (size_t)t;
    asm volatile(
        "st.global.v8.f32 [%0], {%1,%2,%3,%4,%5,%6,%7,%8};"
        :: "l"(o),
           "f"(f[0]), "f"(f[1]), "f"(f[2]), "f"(f[3]),
           "f"(f[4]), "f"(f[5]), "f"(f[6]), "f"(f[7])
        : "memory");
    asm volatile(
        "st.global.v8.f32 [%0], {%1,%2,%3,%4,%5,%6,%7,%8};"
        :: "l"(o + 8),
           "f"(f[8]),  "f"(f[9]),  "f"(f[10]), "f"(f[11]),
           "f"(f[12]), "f"(f[13]), "f"(f[14]), "f"(f[15])
        : "memory");
}

extern "C" void kernel_launch(void* const* d_in, const int* in_sizes, int n_in,
                              void* d_out, int out_size)
{
    const uint32_t* packed = (const uint32_t*)d_in[0];
    const float*    scale  = (const float*)d_in[1];
    float*          out    = (float*)d_out;

    int4_dequant_kernel<<<BLOCKS, THREADS>>>(packed, scale, out);
}